// round 14
// baseline (speedup 1.0000x reference)
#include <cuda_runtime.h>
#include <math.h>

#define BB 2
#define CC 128
#define NXY 4096
#define NN 8192            // nodes per batch (x then y)
#define KTOT 12
#define MROWS (BB*NN)      // 16384

typedef unsigned long long u64;

// packed fp32x2 helpers (Blackwell f32x2 pipe; only reachable via PTX)
__device__ __forceinline__ void fma2(u64& acc, u64 a, u64 b) {
    asm("fma.rn.f32x2 %0, %1, %2, %0;" : "+l"(acc) : "l"(a), "l"(b));
}
__device__ __forceinline__ u64 pk2(float x) {
    u64 r; asm("mov.b64 %0, {%1, %1};" : "=l"(r) : "f"(x)); return r;
}
__device__ __forceinline__ u64 pk2p(float x, float y) {
    u64 r; asm("mov.b64 %0, {%1, %2};" : "=l"(r) : "f"(x), "f"(y)); return r;
}
__device__ __forceinline__ float2 upk(u64 p) {
    float2 r; asm("mov.b64 {%0, %1}, %2;" : "=f"(r.x), "=f"(r.y) : "l"(p)); return r;
}

// ---------------- scratch (device globals; no allocation allowed) -------------
__device__ float g_feat [MROWS*CC];  // 8 MB  [b][node][c]
__device__ float g_featT[CC*MROWS];  // 8 MB  [c][b*NN+node]  (for knn fills)
__device__ float g_rel [MROWS*CC];   // 8 MB
__device__ float g_out [MROWS*CC];   // 8 MB
__device__ float g_norm[MROWS];
__device__ int   g_nbr [MROWS*KTOT];
__device__ float g_sum[CC];
__device__ float g_sumsq[CC];
// half-range partial top-9 lists: [b][mode][half][u][q]
__device__ float g_pd[BB*4*2*9*NXY];   // 2.36 MB
__device__ int   g_pi[BB*4*2*9*NXY];   // 2.36 MB

// ---------------- 1) transpose inputs -> feat [B,N,C] and featT [C, B*N] -----
__global__ void build_feat(const float* __restrict__ x, const float* __restrict__ y) {
    const int b = blockIdx.z, part = blockIdx.y;
    const int n0 = blockIdx.x * 32;
    const float* src = part ? y : x;            // [B][C][NXY]
    __shared__ float s[CC * 33];
    const int t = threadIdx.x;
#pragma unroll
    for (int p = 0; p < 16; ++p) {
        int c  = p * 8 + (t >> 5);
        int nn = t & 31;
        float v = src[(size_t)(b * CC + c) * NXY + n0 + nn];
        s[c * 33 + nn] = v;
        g_featT[(size_t)c * MROWS + b * NN + part * NXY + n0 + nn] = v;
    }
    __syncthreads();
    const int nodeb = part * NXY + n0;
#pragma unroll
    for (int p = 0; p < 16; ++p) {
        int nn = p * 2 + (t >> 7);
        int c  = t & 127;
        g_feat[(size_t)(b * NN + nodeb + nn) * CC + c] = s[c * 33 + nn];
    }
}

// ---------------- 2) per-node squared norms ----------------------------------
__global__ void calc_norm() {
    const int node = blockIdx.x * 8 + (threadIdx.x >> 5);
    const int lane = threadIdx.x & 31;
    const float* f = g_feat + (size_t)node * CC;
    float s = 0.f;
#pragma unroll
    for (int i = 0; i < 4; ++i) { float v = f[lane + 32 * i]; s += v * v; }
#pragma unroll
    for (int o = 16; o; o >>= 1) s += __shfl_down_sync(0xffffffffu, s, o);
    if (!lane) g_norm[node] = s;
}

// pad so knn_all is launch index 3 (the launch ncu samples)
__global__ void prof_pad() {}

// ---------------- 3) fused distance-GEMM + streaming top-K, ALL 4 modes ------
// Ranking score: ||c||^2 - 2*<q,c>  (query-norm term is rank-invariant).
// grid: (NXY/128, 4, BB*2). mode 0: x->x  1: y->y (K9,slot0)
//                           mode 2: x->y  3: y->x (K3,slot9)
// blockIdx.z = b*2 + half; each block scans candidate half-range [h*2048, +2048)
// and emits an ordered top-9 partial list per query to g_pd/g_pi.
// 128 queries x 128 candidates per j0 step, 256 threads, 8q x 8c micro-tile.
// dynamic smem layout (floats):
#define OQ   0          // sQ [32][132]  (128 queries, k-major)
#define OC   4224       // sC [32][132]  (128 cands,  k-major)
#define OD   8448       // sD [128][132] scores
#define ONRM 25344      // sNrm[128]
#define KNN_FLOATS 25472
#define KNN_SMEM (KNN_FLOATS * 4)

__global__ void __launch_bounds__(256, 2) knn_all() {
    extern __shared__ float smem[];
    float* sQ   = smem + OQ;
    float* sC   = smem + OC;
    float* sD   = smem + OD;
    float* sNrm = smem + ONRM;
    float* sMD  = smem;                     // overlay (merge): [128][18] floats
    int*   sMI  = (int*)(smem + 2304);      // overlay (merge): [128][18] ints

    const int zb = blockIdx.z;
    const int b = zb >> 1, half = zb & 1;
    const int mode = blockIdx.y;
    const int qb = (mode & 1) ? NXY : 0;
    const int cb = ((mode + 1) & 2) ? NXY : 0;
    const int q0 = blockIdx.x * 128;
    const int t  = threadIdx.x;
    const int tx = t & 15, ty = t >> 4;

    const int qnode0 = b * NN + qb + q0;      // featT column base for queries
    const int cnodeB = b * NN + cb;           // featT column base for cands
    const float* nr = g_norm + b * NN;

    float ld[9]; int li[9];
#pragma unroll
    for (int u = 0; u < 9; ++u) { ld[u] = 3.4e38f; li[u] = 0; }

    // acc[jj][j][p]: cand (jj*64 + tx*4 + j), query pair (ty*8+2p, ty*8+2p+1)
    u64 acc[2][4][4];

    const int jlo = half * (NXY / 2), jhi = jlo + NXY / 2;
    for (int j0 = jlo; j0 < jhi; j0 += 128) {
        if (t < 128) sNrm[t] = nr[cb + j0 + t];
#pragma unroll
        for (int jj = 0; jj < 2; ++jj)
#pragma unroll
            for (int j = 0; j < 4; ++j)
#pragma unroll
                for (int p = 0; p < 4; ++p) acc[jj][j][p] = 0ull;

        for (int kc = 0; kc < CC; kc += 32) {
            __syncthreads();
#pragma unroll
            for (int u = 0; u < 4; ++u) {          // fill sQ: 32 k-rows x 128 q
                int idx = t + 256 * u;
                int row = idx >> 5, col4 = (idx & 31) * 4;
                *(float4*)&sQ[row * 132 + col4] =
                    *(const float4*)&g_featT[(size_t)(kc + row) * MROWS + qnode0 + col4];
            }
#pragma unroll
            for (int u = 0; u < 4; ++u) {          // fill sC: 32 k-rows x 128 c
                int idx = t + 256 * u;
                int row = idx >> 5, col4 = (idx & 31) * 4;
                *(float4*)&sC[row * 132 + col4] =
                    *(const float4*)&g_featT[(size_t)(kc + row) * MROWS + cnodeB + j0 + col4];
            }
            __syncthreads();
#pragma unroll
            for (int k = 0; k < 32; ++k) {
                const u64* qp = (const u64*)(sQ + k * 132 + ty * 8);
                u64 q01 = qp[0], q23 = qp[1], q45 = qp[2], q67 = qp[3];
                float4 c0 = *(const float4*)(sC + k * 132 + tx * 4);
                float4 c1 = *(const float4*)(sC + k * 132 + 64 + tx * 4);
                u64 cc0 = pk2(c0.x), cc1 = pk2(c0.y), cc2 = pk2(c0.z), cc3 = pk2(c0.w);
                u64 cc4 = pk2(c1.x), cc5 = pk2(c1.y), cc6 = pk2(c1.z), cc7 = pk2(c1.w);
                fma2(acc[0][0][0], q01, cc0); fma2(acc[0][0][1], q23, cc0);
                fma2(acc[0][0][2], q45, cc0); fma2(acc[0][0][3], q67, cc0);
                fma2(acc[0][1][0], q01, cc1); fma2(acc[0][1][1], q23, cc1);
                fma2(acc[0][1][2], q45, cc1); fma2(acc[0][1][3], q67, cc1);
                fma2(acc[0][2][0], q01, cc2); fma2(acc[0][2][1], q23, cc2);
                fma2(acc[0][2][2], q45, cc2); fma2(acc[0][2][3], q67, cc2);
                fma2(acc[0][3][0], q01, cc3); fma2(acc[0][3][1], q23, cc3);
                fma2(acc[0][3][2], q45, cc3); fma2(acc[0][3][3], q67, cc3);
                fma2(acc[1][0][0], q01, cc4); fma2(acc[1][0][1], q23, cc4);
                fma2(acc[1][0][2], q45, cc4); fma2(acc[1][0][3], q67, cc4);
                fma2(acc[1][1][0], q01, cc5); fma2(acc[1][1][1], q23, cc5);
                fma2(acc[1][1][2], q45, cc5); fma2(acc[1][1][3], q67, cc5);
                fma2(acc[1][2][0], q01, cc6); fma2(acc[1][2][1], q23, cc6);
                fma2(acc[1][2][2], q45, cc6); fma2(acc[1][2][3], q67, cc6);
                fma2(acc[1][3][0], q01, cc7); fma2(acc[1][3][1], q23, cc7);
                fma2(acc[1][3][2], q45, cc7); fma2(acc[1][3][3], q67, cc7);
            }
        }
        // stage scores: each thread writes 8q x 8c
        float4 nrm0 = *(const float4*)(sNrm + tx * 4);
        float4 nrm1 = *(const float4*)(sNrm + 64 + tx * 4);
#pragma unroll
        for (int p = 0; p < 4; ++p) {
            int q = ty * 8 + 2 * p;
            float2 a0 = upk(acc[0][0][p]), a1 = upk(acc[0][1][p]);
            float2 a2 = upk(acc[0][2][p]), a3 = upk(acc[0][3][p]);
            float4 lo, hi;
            lo.x = nrm0.x - 2.f * a0.x; hi.x = nrm0.x - 2.f * a0.y;
            lo.y = nrm0.y - 2.f * a1.x; hi.y = nrm0.y - 2.f * a1.y;
            lo.z = nrm0.z - 2.f * a2.x; hi.z = nrm0.z - 2.f * a2.y;
            lo.w = nrm0.w - 2.f * a3.x; hi.w = nrm0.w - 2.f * a3.y;
            *(float4*)(sD + (size_t)q * 132 + tx * 4) = lo;
            *(float4*)(sD + (size_t)(q + 1) * 132 + tx * 4) = hi;
            float2 b0 = upk(acc[1][0][p]), b1 = upk(acc[1][1][p]);
            float2 b2 = upk(acc[1][2][p]), b3 = upk(acc[1][3][p]);
            float4 lo1, hi1;
            lo1.x = nrm1.x - 2.f * b0.x; hi1.x = nrm1.x - 2.f * b0.y;
            lo1.y = nrm1.y - 2.f * b1.x; hi1.y = nrm1.y - 2.f * b1.y;
            lo1.z = nrm1.z - 2.f * b2.x; hi1.z = nrm1.z - 2.f * b2.y;
            lo1.w = nrm1.w - 2.f * b3.x; hi1.w = nrm1.w - 2.f * b3.y;
            *(float4*)(sD + (size_t)q * 132 + 64 + tx * 4) = lo1;
            *(float4*)(sD + (size_t)(q + 1) * 132 + 64 + tx * 4) = hi1;
        }
        __syncthreads();
        // scan: scanner (q = t&127, ch = t>>7) owns 64 cands
        {
            const int sq = t & 127, ch = t >> 7;
            const float* row = sD + (size_t)sq * 132 + ch * 64;
            const int cbase = j0 + ch * 64;
#pragma unroll
            for (int m = 0; m < 64; ++m) {
                float s = row[m];
                if (s < ld[8]) {
                    int jidx = cbase + m;
                    int p = 8;
#pragma unroll
                    for (int u = 7; u >= 0; --u)
                        if (s < ld[u]) { ld[u + 1] = ld[u]; li[u + 1] = li[u]; p = u; }
                    ld[p] = s; li[p] = jidx;
                }
            }
        }
        __syncthreads();   // sD reused next j0 after staging
    }
    // merge two scanner lists per query -> ordered top-9 partial to global
    {
        const int sq = t & 127, ch = t >> 7;
#pragma unroll
        for (int u = 0; u < 9; ++u) {
            sMD[(sq * 2 + ch) * 9 + u] = ld[u];
            sMI[(sq * 2 + ch) * 9 + u] = li[u];
        }
    }
    __syncthreads();
    if (t < 128) {
        float d[18]; int ix[18];
#pragma unroll
        for (int u = 0; u < 18; ++u) { d[u] = sMD[t * 18 + u]; ix[u] = sMI[t * 18 + u]; }
        const size_t pbase = (((size_t)(b * 4 + mode) * 2 + half) * 9) * NXY + q0 + t;
        unsigned used = 0;
#pragma unroll
        for (int m = 0; m < 9; ++m) {
            float bd = 3.5e38f; int best = 0;
#pragma unroll
            for (int u = 0; u < 18; ++u)
                if (!((used >> u) & 1u) && d[u] < bd) { bd = d[u]; best = u; }
            used |= 1u << best;
            g_pd[pbase + (size_t)m * NXY] = bd;
            g_pi[pbase + (size_t)m * NXY] = ix[best];
        }
    }
}

// ---------------- 3b) merge the two half-range partials -> g_nbr -------------
__global__ void knn_merge2() {
    const int tid = blockIdx.x * 256 + threadIdx.x;   // BB*4*NXY = 32768
    const int q = tid & (NXY - 1);
    const int mode = (tid >> 12) & 3;
    const int b = tid >> 14;
    const int qb = (mode & 1) ? NXY : 0;
    const int cb = ((mode + 1) & 2) ? NXY : 0;
    const int slot = (mode < 2) ? 0 : 9;
    const int KW = (mode < 2) ? 9 : 3;

    float d[18]; int ix[18];
#pragma unroll
    for (int h = 0; h < 2; ++h)
#pragma unroll
        for (int u = 0; u < 9; ++u) {
            size_t off = (((size_t)(b * 4 + mode) * 2 + h) * 9 + u) * NXY + q;
            d[h * 9 + u] = g_pd[off];
            ix[h * 9 + u] = g_pi[off];
        }
    int* dst = g_nbr + (size_t)(b * NN + qb + q) * KTOT + slot;
    unsigned used = 0;
    for (int m = 0; m < KW; ++m) {
        float bd = 3.5e38f; int best = 0;
#pragma unroll
        for (int u = 0; u < 18; ++u)
            if (!((used >> u) & 1u) && d[u] < bd) { bd = d[u]; best = u; }
        used |= 1u << best;
        dst[m] = cb + ix[best];
    }
}

// ---------------- 4) max-relative gather -------------------------------------
__global__ void rel_kernel() {
    const int r = blockIdx.x;           // 0..MROWS-1
    const int b = r >> 13;              // NN = 8192
    const int c = threadIdx.x;
    const int* nb = g_nbr + (size_t)r * KTOT;
    const float* fb = g_feat + (size_t)b * NN * CC;
    float m = -3.4e38f;
#pragma unroll
    for (int k = 0; k < KTOT; ++k) {
        int j = nb[k];
        m = fmaxf(m, fb[(size_t)j * CC + c]);
    }
    g_rel[(size_t)r * CC + c] = m - g_feat[(size_t)r * CC + c];
}

// ---------------- 5) 1x1 conv: out = [feat|rel] @ W[l]^T + b -----------------
__global__ void __launch_bounds__(256) conv_kernel(const float* __restrict__ W,
                                                   const float* __restrict__ bias, int l) {
    const int r0 = blockIdx.x * 64;
    const int t = threadIdx.x;
    const int ty = t >> 5, tx = t & 31;
    __shared__ float sH[64 * 33];
    __shared__ float sW[32 * 132];   // [k][channel]
    const float* Wl = W + (size_t)l * CC * 2 * CC;
    u64 acc2[8][2];
#pragma unroll
    for (int i = 0; i < 8; ++i) { acc2[i][0] = 0ull; acc2[i][1] = 0ull; }

    for (int kc = 0; kc < 2 * CC; kc += 32) {
        __syncthreads();
        const float* src = kc < CC ? g_feat : g_rel;
        const int ko = kc < CC ? kc : kc - CC;
#pragma unroll
        for (int u = 0; u < 8; ++u) {
            int e = t + 256 * u; int row = e >> 5, k = e & 31;
            sH[row * 33 + k] = src[(size_t)(r0 + row) * CC + ko + k];
        }
#pragma unroll
        for (int u = 0; u < 4; ++u) {          // 128c x 8 k-groups of 4
            int e = t + 256 * u;
            int c = e >> 3, kg = e & 7;
            float4 w4 = *(const float4*)&Wl[(size_t)c * 2 * CC + kc + kg * 4];
            sW[(kg * 4 + 0) * 132 + c] = w4.x;
            sW[(kg * 4 + 1) * 132 + c] = w4.y;
            sW[(kg * 4 + 2) * 132 + c] = w4.z;
            sW[(kg * 4 + 3) * 132 + c] = w4.w;
        }
        __syncthreads();
#pragma unroll
        for (int k = 0; k < 32; ++k) {
            float4 w4 = *(const float4*)(sW + k * 132 + tx * 4);
            u64 w0 = pk2p(w4.x, w4.y);
            u64 w1 = pk2p(w4.z, w4.w);
#pragma unroll
            for (int i = 0; i < 8; ++i) {
                u64 ap = pk2(sH[(ty + 8 * i) * 33 + k]);
                fma2(acc2[i][0], ap, w0);
                fma2(acc2[i][1], ap, w1);
            }
        }
    }
    float4 bv = *(const float4*)&bias[l * CC + tx * 4];
#pragma unroll
    for (int i = 0; i < 8; ++i) {
        float2 p0 = upk(acc2[i][0]);
        float2 p1 = upk(acc2[i][1]);
        float4 o; o.x = p0.x + bv.x; o.y = p0.y + bv.y; o.z = p1.x + bv.z; o.w = p1.y + bv.w;
        *(float4*)&g_out[(size_t)(r0 + ty + 8 * i) * CC + tx * 4] = o;
    }
}

// ---------------- 6) batchnorm stats -----------------------------------------
__global__ void zero_stats() {
    int t = threadIdx.x;
    if (t < CC) { g_sum[t] = 0.f; g_sumsq[t] = 0.f; }
}

__global__ void stats_kernel() {
    const int r0 = blockIdx.x * 128;
    const int t = threadIdx.x;
    const int c = t & 127, half = t >> 7;
    float s = 0.f, ss = 0.f;
#pragma unroll 4
    for (int i = 0; i < 64; ++i) {
        float v = g_out[(size_t)(r0 + half + 2 * i) * CC + c];
        s += v; ss += v * v;
    }
    __shared__ float aS[256], aSS[256];
    aS[t] = s; aSS[t] = ss;
    __syncthreads();
    if (t < 128) {
        atomicAdd(&g_sum[c],   aS[t] + aS[t + 128]);
        atomicAdd(&g_sumsq[c], aSS[t] + aSS[t + 128]);
    }
}

// ---------------- 7) BN + tanh-GELU + residual (in place on feat) ------------
__global__ void bn_apply(const float* __restrict__ gamma, const float* __restrict__ beta, int l) {
    const int i = blockIdx.x * 256 + threadIdx.x;   // MROWS*CC elems exactly
    const int c = i & 127;
    const float inv_n = 1.f / (float)MROWS;
    float mean = g_sum[c] * inv_n;
    float var  = g_sumsq[c] * inv_n - mean * mean;
    float sc = rsqrtf(var + 1e-5f) * gamma[l * CC + c];
    float v = (g_out[i] - mean) * sc + beta[l * CC + c];
    float g = 0.5f * v * (1.f + tanhf(0.7978845608f * (v + 0.044715f * v * v * v)));
    g_feat[i] += g;
}

// ---------------- 8) transpose feat -> output [B,C,NX,1] ++ [B,C,NY,1] -------
__global__ void write_out(float* __restrict__ out) {
    const int b = blockIdx.z, part = blockIdx.y;
    const int n0 = blockIdx.x * 32;
    const int t = threadIdx.x;
    __shared__ float s[32 * 129];
#pragma unroll
    for (int p = 0; p < 16; ++p) {
        int nn = p * 2 + (t >> 7), c = t & 127;
        s[nn * 129 + c] = g_feat[(size_t)(b * NN + part * NXY + n0 + nn) * CC + c];
    }
    __syncthreads();
    float* dst = out + (size_t)part * BB * CC * NXY;
#pragma unroll
    for (int p = 0; p < 16; ++p) {
        int c = p * 8 + (t >> 5), nn = t & 31;
        dst[(size_t)(b * CC + c) * NXY + n0 + nn] = s[nn * 129 + c];
    }
}

// ---------------- launch ------------------------------------------------------
extern "C" void kernel_launch(void* const* d_in, const int* in_sizes, int n_in,
                              void* d_out, int out_size) {
    const float* x     = (const float*)d_in[0];
    const float* y     = (const float*)d_in[1];
    const float* W     = (const float*)d_in[2];
    const float* bias  = (const float*)d_in[3];
    const float* gamma = (const float*)d_in[4];
    const float* beta  = (const float*)d_in[5];

    cudaFuncSetAttribute(knn_all, cudaFuncAttributeMaxDynamicSharedMemorySize, KNN_SMEM);

    build_feat<<<dim3(NXY / 32, 2, BB), 256>>>(x, y);            // launch 0
    calc_norm<<<MROWS / 8, 256>>>();                             // launch 1
    prof_pad<<<1, 32>>>();                                       // launch 2
    knn_all<<<dim3(NXY / 128, 4, BB * 2), 256, KNN_SMEM>>>();    // launch 3 (ncu)
    knn_merge2<<<BB * 4 * NXY / 256, 256>>>();

    for (int l = 0; l < 2; ++l) {
        rel_kernel<<<MROWS, 128>>>();
        conv_kernel<<<MROWS / 64, 256>>>(W, bias, l);
        zero_stats<<<1, 128>>>();
        stats_kernel<<<128, 256>>>();
        bn_apply<<<MROWS * CC / 256, 256>>>(gamma, beta, l);
    }

    write_out<<<dim3(NXY / 32, 2, BB), 256>>>((float*)d_out);
}

// round 15
// speedup vs baseline: 1.1921x; 1.1921x over previous
#include <cuda_runtime.h>
#include <math.h>

#define BB 2
#define CC 128
#define NXY 4096
#define NN 8192            // nodes per batch (x then y)
#define KTOT 12
#define MROWS (BB*NN)      // 16384

typedef unsigned long long u64;

// packed fp32x2 helpers (Blackwell f32x2 pipe; only reachable via PTX)
__device__ __forceinline__ void fma2(u64& acc, u64 a, u64 b) {
    asm("fma.rn.f32x2 %0, %1, %2, %0;" : "+l"(acc) : "l"(a), "l"(b));
}
__device__ __forceinline__ u64 pk2(float x) {
    u64 r; asm("mov.b64 %0, {%1, %1};" : "=l"(r) : "f"(x)); return r;
}
__device__ __forceinline__ u64 pk2p(float x, float y) {
    u64 r; asm("mov.b64 %0, {%1, %2};" : "=l"(r) : "f"(x), "f"(y)); return r;
}
__device__ __forceinline__ float2 upk(u64 p) {
    float2 r; asm("mov.b64 {%0, %1}, %2;" : "=f"(r.x), "=f"(r.y) : "l"(p)); return r;
}
// 16-byte async copy global->shared (LDGSTS)
__device__ __forceinline__ void cpa16(unsigned saddr, const void* g) {
    asm volatile("cp.async.cg.shared.global [%0], [%1], 16;" :: "r"(saddr), "l"(g));
}
#define CPA_COMMIT() asm volatile("cp.async.commit_group;" ::: "memory")
#define CPA_WAIT(N)  asm volatile("cp.async.wait_group %0;" :: "n"(N) : "memory")

// ---------------- scratch (device globals; no allocation allowed) -------------
__device__ float g_feat [MROWS*CC];  // 8 MB  [b][node][c]
__device__ float g_featT[CC*MROWS];  // 8 MB  [c][b*NN+node]  (for knn fills)
__device__ float g_rel [MROWS*CC];   // 8 MB
__device__ float g_out [MROWS*CC];   // 8 MB
__device__ float g_norm[MROWS];
__device__ int   g_nbr [MROWS*KTOT];
__device__ float g_sum[CC];
__device__ float g_sumsq[CC];

// ---------------- 1) transpose inputs -> feat [B,N,C] and featT [C, B*N] -----
__global__ void build_feat(const float* __restrict__ x, const float* __restrict__ y) {
    const int b = blockIdx.z, part = blockIdx.y;
    const int n0 = blockIdx.x * 32;
    const float* src = part ? y : x;            // [B][C][NXY]
    __shared__ float s[CC * 33];
    const int t = threadIdx.x;
#pragma unroll
    for (int p = 0; p < 16; ++p) {
        int c  = p * 8 + (t >> 5);
        int nn = t & 31;
        float v = src[(size_t)(b * CC + c) * NXY + n0 + nn];
        s[c * 33 + nn] = v;
        g_featT[(size_t)c * MROWS + b * NN + part * NXY + n0 + nn] = v;
    }
    __syncthreads();
    const int nodeb = part * NXY + n0;
#pragma unroll
    for (int p = 0; p < 16; ++p) {
        int nn = p * 2 + (t >> 7);
        int c  = t & 127;
        g_feat[(size_t)(b * NN + nodeb + nn) * CC + c] = s[c * 33 + nn];
    }
}

// ---------------- 2) per-node squared norms ----------------------------------
__global__ void calc_norm() {
    const int node = blockIdx.x * 8 + (threadIdx.x >> 5);
    const int lane = threadIdx.x & 31;
    const float* f = g_feat + (size_t)node * CC;
    float s = 0.f;
#pragma unroll
    for (int i = 0; i < 4; ++i) { float v = f[lane + 32 * i]; s += v * v; }
#pragma unroll
    for (int o = 16; o; o >>= 1) s += __shfl_down_sync(0xffffffffu, s, o);
    if (!lane) g_norm[node] = s;
}

// pad so knn_all is launch index 3 (the launch ncu samples)
__global__ void prof_pad() {}

// ---------------- 3) fused distance-GEMM + streaming top-K, ALL 4 modes ------
// Ranking score: ||c||^2 - 2*<q,c>  (query-norm term is rank-invariant).
// grid: (NXY/128, 4, BB). mode 0: x->x  1: y->y (K9,slot0)
//                         mode 2: x->y  3: y->x (K3,slot9)
// 128 queries x 128 candidates per j0 step, 256 threads, 8q x 8c micro-tile.
// Fills: cp.async double-buffered; buffer B lives in the (then-unused) sD area.
// dynamic smem layout (floats):
#define OQ   0          // bufA sQ [32][132]
#define OC   4224       // bufA sC [32][132]
#define OD   8448       // sD [128][132]; bufB sQ=OD, sC=OD+4224 during kc loop
#define ONRM 25344      // sNrm[128]
#define KNN_FLOATS 25472
#define KNN_SMEM (KNN_FLOATS * 4)

__global__ void __launch_bounds__(256, 2) knn_all() {
    extern __shared__ float smem[];
    float* sD   = smem + OD;
    float* sNrm = smem + ONRM;
    float* sMD  = smem;                     // overlay (merge): [128][18] floats
    int*   sMI  = (int*)(smem + 2304);      // overlay (merge): [128][18] ints
    const unsigned sbase = (unsigned)__cvta_generic_to_shared(smem);

    const int b = blockIdx.z, mode = blockIdx.y;
    const int qb = (mode & 1) ? NXY : 0;
    const int cb = ((mode + 1) & 2) ? NXY : 0;
    const int slot = (mode < 2) ? 0 : 9;
    const int KW = (mode < 2) ? 9 : 3;
    const int q0 = blockIdx.x * 128;
    const int t  = threadIdx.x;
    const int tx = t & 15, ty = t >> 4;

    const int qnode0 = b * NN + qb + q0;      // featT column base for queries
    const int cnodeB = b * NN + cb;           // featT column base for cands
    const float* nr = g_norm + b * NN;

    // per-thread fill coordinates
    const int frow = t >> 5;                  // k-row 0..7 (+8*u)
    const int fcol = (t & 31) * 4;            // node column (float4)

    const int bufQ[2] = {OQ, OD};
    const int bufC[2] = {OC, OD + 4224};

    float ld[9]; int li[9];
#pragma unroll
    for (int u = 0; u < 9; ++u) { ld[u] = 3.4e38f; li[u] = 0; }

    // acc[jj][j][p]: cand (jj*64 + tx*4 + j), query pair (ty*8+2p, ty*8+2p+1)
    u64 acc[2][4][4];

    // prefetch j0=0, chunk 0 into buffer A
#pragma unroll
    for (int u = 0; u < 4; ++u) {
        int row = frow + 8 * u;
        cpa16(sbase + (unsigned)(OQ + row * 132 + fcol) * 4u,
              &g_featT[(size_t)row * MROWS + qnode0 + fcol]);
        cpa16(sbase + (unsigned)(OC + row * 132 + fcol) * 4u,
              &g_featT[(size_t)row * MROWS + cnodeB + 0 + fcol]);
    }
    CPA_COMMIT();

    for (int j0 = 0; j0 < NXY; j0 += 128) {
        if (t < 128) sNrm[t] = nr[cb + j0 + t];
#pragma unroll
        for (int jj = 0; jj < 2; ++jj)
#pragma unroll
            for (int j = 0; j < 4; ++j)
#pragma unroll
                for (int p = 0; p < 4; ++p) acc[jj][j][p] = 0ull;

        for (int kb = 0; kb < 4; ++kb) {
            if (kb < 3) {                    // prefetch next chunk -> other buf
                const int kc = (kb + 1) * 32;
                const int bq = bufQ[(kb + 1) & 1], bc = bufC[(kb + 1) & 1];
#pragma unroll
                for (int u = 0; u < 4; ++u) {
                    int row = frow + 8 * u;
                    cpa16(sbase + (unsigned)(bq + row * 132 + fcol) * 4u,
                          &g_featT[(size_t)(kc + row) * MROWS + qnode0 + fcol]);
                    cpa16(sbase + (unsigned)(bc + row * 132 + fcol) * 4u,
                          &g_featT[(size_t)(kc + row) * MROWS + cnodeB + j0 + fcol]);
                }
                CPA_COMMIT();
                CPA_WAIT(1);
            } else {
                CPA_WAIT(0);
            }
            __syncthreads();
            const float* sQ = smem + bufQ[kb & 1];
            const float* sC = smem + bufC[kb & 1];
#pragma unroll
            for (int k = 0; k < 32; ++k) {
                const u64* qp = (const u64*)(sQ + k * 132 + ty * 8);
                u64 q01 = qp[0], q23 = qp[1], q45 = qp[2], q67 = qp[3];
                float4 c0 = *(const float4*)(sC + k * 132 + tx * 4);
                float4 c1 = *(const float4*)(sC + k * 132 + 64 + tx * 4);
                u64 cc0 = pk2(c0.x), cc1 = pk2(c0.y), cc2 = pk2(c0.z), cc3 = pk2(c0.w);
                u64 cc4 = pk2(c1.x), cc5 = pk2(c1.y), cc6 = pk2(c1.z), cc7 = pk2(c1.w);
                fma2(acc[0][0][0], q01, cc0); fma2(acc[0][0][1], q23, cc0);
                fma2(acc[0][0][2], q45, cc0); fma2(acc[0][0][3], q67, cc0);
                fma2(acc[0][1][0], q01, cc1); fma2(acc[0][1][1], q23, cc1);
                fma2(acc[0][1][2], q45, cc1); fma2(acc[0][1][3], q67, cc1);
                fma2(acc[0][2][0], q01, cc2); fma2(acc[0][2][1], q23, cc2);
                fma2(acc[0][2][2], q45, cc2); fma2(acc[0][2][3], q67, cc2);
                fma2(acc[0][3][0], q01, cc3); fma2(acc[0][3][1], q23, cc3);
                fma2(acc[0][3][2], q45, cc3); fma2(acc[0][3][3], q67, cc3);
                fma2(acc[1][0][0], q01, cc4); fma2(acc[1][0][1], q23, cc4);
                fma2(acc[1][0][2], q45, cc4); fma2(acc[1][0][3], q67, cc4);
                fma2(acc[1][1][0], q01, cc5); fma2(acc[1][1][1], q23, cc5);
                fma2(acc[1][1][2], q45, cc5); fma2(acc[1][1][3], q67, cc5);
                fma2(acc[1][2][0], q01, cc6); fma2(acc[1][2][1], q23, cc6);
                fma2(acc[1][2][2], q45, cc6); fma2(acc[1][2][3], q67, cc6);
                fma2(acc[1][3][0], q01, cc7); fma2(acc[1][3][1], q23, cc7);
                fma2(acc[1][3][2], q45, cc7); fma2(acc[1][3][3], q67, cc7);
            }
            __syncthreads();      // compute of this chunk done before buf reuse
        }

        // prefetch next j0 chunk 0 into buffer A (A is free during stage+scan)
        if (j0 + 128 < NXY) {
#pragma unroll
            for (int u = 0; u < 4; ++u) {
                int row = frow + 8 * u;
                cpa16(sbase + (unsigned)(OQ + row * 132 + fcol) * 4u,
                      &g_featT[(size_t)row * MROWS + qnode0 + fcol]);
                cpa16(sbase + (unsigned)(OC + row * 132 + fcol) * 4u,
                      &g_featT[(size_t)row * MROWS + cnodeB + j0 + 128 + fcol]);
            }
            CPA_COMMIT();
        }

        // stage scores: each thread writes 8q x 8c
        float4 nrm0 = *(const float4*)(sNrm + tx * 4);
        float4 nrm1 = *(const float4*)(sNrm + 64 + tx * 4);
#pragma unroll
        for (int p = 0; p < 4; ++p) {
            int q = ty * 8 + 2 * p;
            float2 a0 = upk(acc[0][0][p]), a1 = upk(acc[0][1][p]);
            float2 a2 = upk(acc[0][2][p]), a3 = upk(acc[0][3][p]);
            float4 lo, hi;
            lo.x = nrm0.x - 2.f * a0.x; hi.x = nrm0.x - 2.f * a0.y;
            lo.y = nrm0.y - 2.f * a1.x; hi.y = nrm0.y - 2.f * a1.y;
            lo.z = nrm0.z - 2.f * a2.x; hi.z = nrm0.z - 2.f * a2.y;
            lo.w = nrm0.w - 2.f * a3.x; hi.w = nrm0.w - 2.f * a3.y;
            *(float4*)(sD + (size_t)q * 132 + tx * 4) = lo;
            *(float4*)(sD + (size_t)(q + 1) * 132 + tx * 4) = hi;
            float2 b0 = upk(acc[1][0][p]), b1 = upk(acc[1][1][p]);
            float2 b2 = upk(acc[1][2][p]), b3 = upk(acc[1][3][p]);
            float4 lo1, hi1;
            lo1.x = nrm1.x - 2.f * b0.x; hi1.x = nrm1.x - 2.f * b0.y;
            lo1.y = nrm1.y - 2.f * b1.x; hi1.y = nrm1.y - 2.f * b1.y;
            lo1.z = nrm1.z - 2.f * b2.x; hi1.z = nrm1.z - 2.f * b2.y;
            lo1.w = nrm1.w - 2.f * b3.x; hi1.w = nrm1.w - 2.f * b3.y;
            *(float4*)(sD + (size_t)q * 132 + 64 + tx * 4) = lo1;
            *(float4*)(sD + (size_t)(q + 1) * 132 + 64 + tx * 4) = hi1;
        }
        __syncthreads();
        // scan: scanner (q = t&127, ch = t>>7) owns 64 cands
        {
            const int sq = t & 127, ch = t >> 7;
            const float* row = sD + (size_t)sq * 132 + ch * 64;
            const int cbase = j0 + ch * 64;
#pragma unroll
            for (int m = 0; m < 64; ++m) {
                float s = row[m];
                if (s < ld[8]) {
                    int jidx = cbase + m;
                    int p = 8;
#pragma unroll
                    for (int u = 7; u >= 0; --u)
                        if (s < ld[u]) { ld[u + 1] = ld[u]; li[u + 1] = li[u]; p = u; }
                    ld[p] = s; li[p] = jidx;
                }
            }
        }
        __syncthreads();   // scan done before next j0 overwrites sD/bufB
    }
    // merge two partial lists per query (overlay region; fills are done)
    {
        const int sq = t & 127, ch = t >> 7;
#pragma unroll
        for (int u = 0; u < 9; ++u) {
            sMD[(sq * 2 + ch) * 9 + u] = ld[u];
            sMI[(sq * 2 + ch) * 9 + u] = li[u];
        }
    }
    __syncthreads();
    if (t < 128) {
        float d[18]; int ix[18];
#pragma unroll
        for (int u = 0; u < 18; ++u) { d[u] = sMD[t * 18 + u]; ix[u] = sMI[t * 18 + u]; }
        int* dst = g_nbr + (size_t)(b * NN + qb + q0 + t) * KTOT + slot;
        unsigned used = 0;
        for (int m = 0; m < KW; ++m) {
            float bd = 3.5e38f; int best = 0;
#pragma unroll
            for (int u = 0; u < 18; ++u)
                if (!((used >> u) & 1u) && d[u] < bd) { bd = d[u]; best = u; }
            used |= 1u << best;
            dst[m] = cb + ix[best];
        }
    }
}

// ---------------- 4) max-relative gather -------------------------------------
__global__ void rel_kernel() {
    const int r = blockIdx.x;           // 0..MROWS-1
    const int b = r >> 13;              // NN = 8192
    const int c = threadIdx.x;
    const int* nb = g_nbr + (size_t)r * KTOT;
    const float* fb = g_feat + (size_t)b * NN * CC;
    float m = -3.4e38f;
#pragma unroll
    for (int k = 0; k < KTOT; ++k) {
        int j = nb[k];
        m = fmaxf(m, fb[(size_t)j * CC + c]);
    }
    g_rel[(size_t)r * CC + c] = m - g_feat[(size_t)r * CC + c];
}

// ---------------- 5) 1x1 conv: out = [feat|rel] @ W[l]^T + b -----------------
__global__ void __launch_bounds__(256) conv_kernel(const float* __restrict__ W,
                                                   const float* __restrict__ bias, int l) {
    const int r0 = blockIdx.x * 64;
    const int t = threadIdx.x;
    const int ty = t >> 5, tx = t & 31;
    __shared__ float sH[64 * 33];
    __shared__ float sW[32 * 132];   // [k][channel]
    const float* Wl = W + (size_t)l * CC * 2 * CC;
    u64 acc2[8][2];
#pragma unroll
    for (int i = 0; i < 8; ++i) { acc2[i][0] = 0ull; acc2[i][1] = 0ull; }

    for (int kc = 0; kc < 2 * CC; kc += 32) {
        __syncthreads();
        const float* src = kc < CC ? g_feat : g_rel;
        const int ko = kc < CC ? kc : kc - CC;
#pragma unroll
        for (int u = 0; u < 8; ++u) {
            int e = t + 256 * u; int row = e >> 5, k = e & 31;
            sH[row * 33 + k] = src[(size_t)(r0 + row) * CC + ko + k];
        }
#pragma unroll
        for (int u = 0; u < 4; ++u) {          // 128c x 8 k-groups of 4
            int e = t + 256 * u;
            int c = e >> 3, kg = e & 7;
            float4 w4 = *(const float4*)&Wl[(size_t)c * 2 * CC + kc + kg * 4];
            sW[(kg * 4 + 0) * 132 + c] = w4.x;
            sW[(kg * 4 + 1) * 132 + c] = w4.y;
            sW[(kg * 4 + 2) * 132 + c] = w4.z;
            sW[(kg * 4 + 3) * 132 + c] = w4.w;
        }
        __syncthreads();
#pragma unroll
        for (int k = 0; k < 32; ++k) {
            float4 w4 = *(const float4*)(sW + k * 132 + tx * 4);
            u64 w0 = pk2p(w4.x, w4.y);
            u64 w1 = pk2p(w4.z, w4.w);
#pragma unroll
            for (int i = 0; i < 8; ++i) {
                u64 ap = pk2(sH[(ty + 8 * i) * 33 + k]);
                fma2(acc2[i][0], ap, w0);
                fma2(acc2[i][1], ap, w1);
            }
        }
    }
    float4 bv = *(const float4*)&bias[l * CC + tx * 4];
#pragma unroll
    for (int i = 0; i < 8; ++i) {
        float2 p0 = upk(acc2[i][0]);
        float2 p1 = upk(acc2[i][1]);
        float4 o; o.x = p0.x + bv.x; o.y = p0.y + bv.y; o.z = p1.x + bv.z; o.w = p1.y + bv.w;
        *(float4*)&g_out[(size_t)(r0 + ty + 8 * i) * CC + tx * 4] = o;
    }
}

// ---------------- 6) batchnorm stats -----------------------------------------
__global__ void zero_stats() {
    int t = threadIdx.x;
    if (t < CC) { g_sum[t] = 0.f; g_sumsq[t] = 0.f; }
}

__global__ void stats_kernel() {
    const int r0 = blockIdx.x * 128;
    const int t = threadIdx.x;
    const int c = t & 127, half = t >> 7;
    float s = 0.f, ss = 0.f;
#pragma unroll 4
    for (int i = 0; i < 64; ++i) {
        float v = g_out[(size_t)(r0 + half + 2 * i) * CC + c];
        s += v; ss += v * v;
    }
    __shared__ float aS[256], aSS[256];
    aS[t] = s; aSS[t] = ss;
    __syncthreads();
    if (t < 128) {
        atomicAdd(&g_sum[c],   aS[t] + aS[t + 128]);
        atomicAdd(&g_sumsq[c], aSS[t] + aSS[t + 128]);
    }
}

// ---------------- 7) BN + tanh-GELU + residual (in place on feat) ------------
__global__ void bn_apply(const float* __restrict__ gamma, const float* __restrict__ beta, int l) {
    const int i = blockIdx.x * 256 + threadIdx.x;   // MROWS*CC elems exactly
    const int c = i & 127;
    const float inv_n = 1.f / (float)MROWS;
    float mean = g_sum[c] * inv_n;
    float var  = g_sumsq[c] * inv_n - mean * mean;
    float sc = rsqrtf(var + 1e-5f) * gamma[l * CC + c];
    float v = (g_out[i] - mean) * sc + beta[l * CC + c];
    float g = 0.5f * v * (1.f + tanhf(0.7978845608f * (v + 0.044715f * v * v * v)));
    g_feat[i] += g;
}

// ---------------- 8) transpose feat -> output [B,C,NX,1] ++ [B,C,NY,1] -------
__global__ void write_out(float* __restrict__ out) {
    const int b = blockIdx.z, part = blockIdx.y;
    const int n0 = blockIdx.x * 32;
    const int t = threadIdx.x;
    __shared__ float s[32 * 129];
#pragma unroll
    for (int p = 0; p < 16; ++p) {
        int nn = p * 2 + (t >> 7), c = t & 127;
        s[nn * 129 + c] = g_feat[(size_t)(b * NN + part * NXY + n0 + nn) * CC + c];
    }
    __syncthreads();
    float* dst = out + (size_t)part * BB * CC * NXY;
#pragma unroll
    for (int p = 0; p < 16; ++p) {
        int c = p * 8 + (t >> 5), nn = t & 31;
        dst[(size_t)(b * CC + c) * NXY + n0 + nn] = s[nn * 129 + c];
    }
}

// ---------------- launch ------------------------------------------------------
extern "C" void kernel_launch(void* const* d_in, const int* in_sizes, int n_in,
                              void* d_out, int out_size) {
    const float* x     = (const float*)d_in[0];
    const float* y     = (const float*)d_in[1];
    const float* W     = (const float*)d_in[2];
    const float* bias  = (const float*)d_in[3];
    const float* gamma = (const float*)d_in[4];
    const float* beta  = (const float*)d_in[5];

    cudaFuncSetAttribute(knn_all, cudaFuncAttributeMaxDynamicSharedMemorySize, KNN_SMEM);

    build_feat<<<dim3(NXY / 32, 2, BB), 256>>>(x, y);        // launch 0
    calc_norm<<<MROWS / 8, 256>>>();                         // launch 1
    prof_pad<<<1, 32>>>();                                   // launch 2
    knn_all<<<dim3(NXY / 128, 4, BB), 256, KNN_SMEM>>>();    // launch 3 (ncu)

    for (int l = 0; l < 2; ++l) {
        rel_kernel<<<MROWS, 128>>>();
        conv_kernel<<<MROWS / 64, 256>>>(W, bias, l);
        zero_stats<<<1, 128>>>();
        stats_kernel<<<128, 256>>>();
        bn_apply<<<MROWS * CC / 256, 256>>>(gamma, beta, l);
    }

    write_out<<<dim3(NXY / 32, 2, BB), 256>>>((float*)d_out);
}